// round 16
// baseline (speedup 1.0000x reference)
#include <cuda_runtime.h>
#include <cuda_fp16.h>
#include <math.h>
#include <stdint.h>

// Problem constants
#define T_TOK 4096
#define H_DIM 2048
#define E_NUM 8
#define I_DIM 768
#define KSEL  2
#define N1    (2*I_DIM)
#define ROWS_TOTAL (T_TOK*KSEL)
#define AUX_COEF 0.001f

// ---------------- scratch (device-code access ONLY — never host args) -------
__device__ uint4 g_x_h4[(size_t)T_TOK * H_DIM / 8];            // fp16 activations
__device__ uint4 g_w1_h4[(size_t)E_NUM * N1 * H_DIM / 8];      // fp16 w1
__device__ uint4 g_w2_h4[(size_t)E_NUM * H_DIM * I_DIM / 8];   // fp16 w2
__device__ uint4 g_i_h4[(size_t)ROWS_TOTAL * I_DIM / 8];       // fp16 inter
__device__ uint4 g_y_h4[(size_t)ROWS_TOTAL * H_DIM / 8];       // fp16 weighted expert out
__device__ int   g_sel[ROWS_TOTAL];
__device__ float g_wt[ROWS_TOTAL];
__device__ int   g_counts[E_NUM];
__device__ int   g_ofs[E_NUM];
__device__ int   g_cursor[E_NUM];
__device__ int   g_rows_tok[ROWS_TOTAL];
__device__ int   g_rows_slot[ROWS_TOTAL];
__device__ float g_rows_w[ROWS_TOTAL];
__device__ float g_prob_sum[E_NUM];

// ---------------- helpers ----------------
__device__ __forceinline__ uint32_t smem_u32(const void* p) {
    uint32_t a;
    asm("{ .reg .u64 t; cvta.to.shared.u64 t, %1; cvt.u32.u64 %0, t; }" : "=r"(a) : "l"(p));
    return a;
}
__device__ __forceinline__ void ldsm_x4(uint32_t* r, uint32_t addr) {
    asm volatile("ldmatrix.sync.aligned.m8n8.x4.shared.b16 {%0,%1,%2,%3}, [%4];"
        : "=r"(r[0]), "=r"(r[1]), "=r"(r[2]), "=r"(r[3]) : "r"(addr));
}
__device__ __forceinline__ void mma16816(float* c, const uint32_t* a, const uint32_t* b) {
    asm volatile("mma.sync.aligned.m16n8k16.row.col.f32.f16.f16.f32 "
        "{%0,%1,%2,%3}, {%4,%5,%6,%7}, {%8,%9}, {%0,%1,%2,%3};"
        : "+f"(c[0]), "+f"(c[1]), "+f"(c[2]), "+f"(c[3])
        : "r"(a[0]), "r"(a[1]), "r"(a[2]), "r"(a[3]), "r"(b[0]), "r"(b[1]));
}
__device__ __forceinline__ void cpa16(uint32_t dst, const void* src) {
    asm volatile("cp.async.cg.shared.global [%0], [%1], 16;" :: "r"(dst), "l"(src) : "memory");
}
#define CP_COMMIT() asm volatile("cp.async.commit_group;" ::: "memory")
#define CP_WAIT1()  asm volatile("cp.async.wait_group 1;" ::: "memory")

// ---------------- fused convert fp32 -> fp16 (x, w1, w2) + init -------------
#define N4_X  (T_TOK * H_DIM / 4)
#define N4_W1 (E_NUM * N1 * H_DIM / 4)
#define N4_W2 (E_NUM * H_DIM * I_DIM / 4)
__global__ void split_all_kernel(const float4* __restrict__ x,
                                 const float4* __restrict__ w1,
                                 const float4* __restrict__ w2) {
    if (blockIdx.x == 0 && threadIdx.x < E_NUM) {
        g_counts[threadIdx.x] = 0; g_prob_sum[threadIdx.x] = 0.f;
    }
    long long i = (long long)blockIdx.x * blockDim.x + threadIdx.x;
    const float4* src; uint2* hi; long long idx;
    if (i < N4_X) {
        src = x;  hi = (uint2*)g_x_h4;  idx = i;
    } else if (i < (long long)N4_X + N4_W1) {
        src = w1; hi = (uint2*)g_w1_h4; idx = i - N4_X;
    } else if (i < (long long)N4_X + N4_W1 + N4_W2) {
        src = w2; hi = (uint2*)g_w2_h4; idx = i - N4_X - N4_W1;
    } else return;
    float4 v = src[idx];
    __half2 hxy = __floats2half2_rn(v.x, v.y);
    __half2 hzw = __floats2half2_rn(v.z, v.w);
    uint2 h;
    h.x = *reinterpret_cast<uint32_t*>(&hxy); h.y = *reinterpret_cast<uint32_t*>(&hzw);
    hi[idx] = h;
}

// ---------------- router (validated) ----------------------------------------
__global__ void router_kernel(const float* __restrict__ x,
                              const float* __restrict__ gw,
                              float* __restrict__ logits_out) {
    const int t = blockIdx.x;
    const float* xr = x + (size_t)t * H_DIM;
    float acc[E_NUM];
#pragma unroll
    for (int e = 0; e < E_NUM; e++) acc[e] = 0.f;
    for (int h = threadIdx.x; h < H_DIM; h += blockDim.x) {
        float xv = xr[h];
        const float4 g0 = *(const float4*)(gw + (size_t)h * E_NUM);
        const float4 g1 = *(const float4*)(gw + (size_t)h * E_NUM + 4);
        acc[0] += xv * g0.x; acc[1] += xv * g0.y; acc[2] += xv * g0.z; acc[3] += xv * g0.w;
        acc[4] += xv * g1.x; acc[5] += xv * g1.y; acc[6] += xv * g1.z; acc[7] += xv * g1.w;
    }
#pragma unroll
    for (int e = 0; e < E_NUM; e++)
#pragma unroll
        for (int o = 16; o; o >>= 1) acc[e] += __shfl_xor_sync(0xffffffffu, acc[e], o);
    __shared__ float red[E_NUM][8];
    int warp = threadIdx.x >> 5, lane = threadIdx.x & 31;
    if (lane == 0)
#pragma unroll
        for (int e = 0; e < E_NUM; e++) red[e][warp] = acc[e];
    __syncthreads();
    if (threadIdx.x == 0) {
        float lg[E_NUM];
#pragma unroll
        for (int e = 0; e < E_NUM; e++) {
            float s = 0.f;
#pragma unroll
            for (int w = 0; w < 8; w++) s += red[e][w];
            lg[e] = s;
        }
        if (logits_out)
#pragma unroll
            for (int e = 0; e < E_NUM; e++) logits_out[(size_t)t * E_NUM + e] = lg[e];
        float mx = lg[0];
#pragma unroll
        for (int e = 1; e < E_NUM; e++) mx = fmaxf(mx, lg[e]);
        float p[E_NUM], s = 0.f;
#pragma unroll
        for (int e = 0; e < E_NUM; e++) { p[e] = expf(lg[e] - mx); s += p[e]; }
        float inv = 1.f / s;
#pragma unroll
        for (int e = 0; e < E_NUM; e++) { p[e] *= inv; atomicAdd(&g_prob_sum[e], p[e]); }
        bool used[E_NUM];
#pragma unroll
        for (int e = 0; e < E_NUM; e++) used[e] = false;
        int si[KSEL]; float sp[KSEL]; float wsum = 0.f;
#pragma unroll
        for (int k = 0; k < KSEL; k++) {
            int bi = -1; float bv = -1.f;
#pragma unroll
            for (int e = 0; e < E_NUM; e++)
                if (!used[e] && p[e] > bv) { bv = p[e]; bi = e; }
            used[bi] = true; si[k] = bi; sp[k] = bv; wsum += bv;
        }
        float winv = 1.f / wsum;
#pragma unroll
        for (int k = 0; k < KSEL; k++) {
            g_sel[t * KSEL + k] = si[k];
            g_wt[t * KSEL + k]  = sp[k] * winv;
            atomicAdd(&g_counts[si[k]], 1);
        }
    }
}

// ---------------- offsets + scatter (single block) --------------------------
__global__ void offsets_scatter_kernel() {
    if (threadIdx.x == 0) {
        int run = 0;
        for (int e = 0; e < E_NUM; e++) { g_ofs[e] = run; g_cursor[e] = run; run += g_counts[e]; }
    }
    __syncthreads();
    for (int i = threadIdx.x; i < ROWS_TOTAL; i += blockDim.x) {
        int e = g_sel[i];
        int p = atomicAdd(&g_cursor[e], 1);
        g_rows_tok[p]  = i / KSEL;
        g_rows_slot[p] = i % KSEL;
        g_rows_w[p]    = g_wt[i];
    }
}

// ---------------- HMMA expert GEMM: CTA 128x256, 8 warps of 64x64 -----------
// 256 threads, occ 1, K-chunk 64, 2-stage cp.async.
// LDSM traffic: 128 B/MMA (vs 192 at 64x32) — crossbar relief.
// MODE 1: B tile = 128 gate rows + 128 up rows of same 128 inter cols.
// smem row stride 72 fp16 (144 B) — conflict-free (R13-proven).
#define SROW 72
#define A_ARR (128 * 144)              // 18432
#define B_ARR (256 * 144)              // 36864
#define OFF_A  0
#define OFF_B  A_ARR
#define STG_BYTES (A_ARR + B_ARR)      // 55296
#define SMEM_TOT (2 * STG_BYTES)       // 110592

template<int KDIM, int MODE>
__global__ void __launch_bounds__(256, 1)
moe_gemm_mma() {
    constexpr int NCH  = KDIM / 64;
    constexpr int NDIM = (MODE == 1) ? N1 : H_DIM;
    const __half* a_h = (MODE == 1) ? (const __half*)g_x_h4 : (const __half*)g_i_h4;
    const __half* b_h = (MODE == 1) ? (const __half*)g_w1_h4 : (const __half*)g_w2_h4;

    const int e   = blockIdx.z;
    const int cnt = g_counts[e];
    const int m0  = blockIdx.x * 128;
    if (m0 >= cnt) return;
    const int nb  = blockIdx.y;
    const int ofs = g_ofs[e];

    extern __shared__ char smem[];
    const uint32_t sb = smem_u32(smem);

    const int tid  = threadIdx.x;
    const int wid  = tid >> 5;
    const int lane = tid & 31;
    const int wm   = wid & 1;     // 2 m-halves of 64
    const int wn   = wid >> 1;    // 4 n-quarters of 64

    // ---- loader: rows 128B (64 fp16) = 8x16B; A 4/thr, B 8/thr -------------
    const int q16 = tid & 7;
    const int r0  = tid >> 3;                    // base row 0..31
    const uint32_t soff0 = (uint32_t)(r0 * 144 + q16 * 16);
    uint32_t arow[4], brow[8];
#pragma unroll
    for (int i = 0; i < 4; i++) {
        int r = i * 32 + r0;                     // 0..127
        int lm = m0 + r; if (lm > cnt - 1) lm = cnt - 1;
        if (MODE == 1) arow[i] = (uint32_t)__ldg(&g_rows_tok[ofs + lm]) * H_DIM + q16 * 8;
        else           arow[i] = (uint32_t)(ofs + lm) * I_DIM + q16 * 8;
    }
#pragma unroll
    for (int j = 0; j < 8; j++) {
        int r = j * 32 + r0;                     // 0..255
        int gn;
        if (MODE == 1) gn = (r < 128) ? (nb * 128 + r) : (I_DIM + nb * 128 + (r - 128));
        else           gn = nb * 256 + r;
        brow[j] = (uint32_t)((e * NDIM + gn) * KDIM) + q16 * 8;
    }

    auto issue_stage = [&](int c) {
        if (c < NCH) {
            const int kt = c * 64;
            const uint32_t st = sb + (uint32_t)(c & 1) * STG_BYTES;
#pragma unroll
            for (int i = 0; i < 4; i++)
                cpa16(st + OFF_A + soff0 + i * (32 * 144), a_h + arow[i] + kt);
#pragma unroll
            for (int j = 0; j < 8; j++)
                cpa16(st + OFF_B + soff0 + j * (32 * 144), b_h + brow[j] + kt);
        }
        CP_COMMIT();
    };

    // ldmatrix per-thread base byte offsets (R9-proven 64-wide wn; SROW=72)
    const uint32_t a_base = ((wm * 64 + (lane & 15)) * SROW + (lane >> 4) * 8) * 2;
    const uint32_t b_base = ((wn * 64 + ((lane >> 4) << 3) + (lane & 7)) * SROW + ((lane >> 3) & 1) * 8) * 2;

    float acc[4][8][4];
#pragma unroll
    for (int i = 0; i < 4; i++)
#pragma unroll
        for (int j = 0; j < 8; j++)
#pragma unroll
            for (int k = 0; k < 4; k++) acc[i][j][k] = 0.f;

    issue_stage(0); issue_stage(1);

    for (int c = 0; c < NCH; c++) {
        CP_WAIT1();            // stage c landed (only c+1 pending)
        __syncthreads();

        const uint32_t stg = sb + (uint32_t)(c & 1) * STG_BYTES;
#pragma unroll
        for (int kk = 0; kk < 4; kk++) {
            const uint32_t koff = kk * 32;     // 16 fp16 = 32 B
            uint32_t af[4][4], bf[4][4];
#pragma unroll
            for (int im = 0; im < 4; im++)
                ldsm_x4(af[im], stg + OFF_A + a_base + im * (16 * SROW * 2) + koff);
#pragma unroll
            for (int g = 0; g < 4; g++)
                ldsm_x4(bf[g], stg + OFF_B + b_base + g * (16 * SROW * 2) + koff);
            // 32 MMAs, all distinct accumulators (full ILP)
#pragma unroll
            for (int im = 0; im < 4; im++)
#pragma unroll
                for (int g = 0; g < 4; g++) {
                    mma16816(acc[im][g * 2 + 0], af[im], &bf[g][0]);
                    mma16816(acc[im][g * 2 + 1], af[im], &bf[g][2]);
                }
        }
        __syncthreads();       // all warps done with slot c&1
        issue_stage(c + 2);    // refill it
    }

    // ---------------- epilogue ----------------
    if (MODE == 1) {
        // gate warps (wn<2, cols 0..127) stage to smem; up warps fuse silu
        float* Cs = (float*)smem;   // 128x128 fp32 = 64 KB (reads done)
        if (wn < 2) {
#pragma unroll
            for (int im = 0; im < 4; im++)
#pragma unroll
                for (int jn = 0; jn < 8; jn++) {
                    int row = wm * 64 + im * 16 + (lane >> 2);
                    int col = wn * 64 + jn * 8 + (lane & 3) * 2;
                    *(float2*)&Cs[row * 128 + col]       = make_float2(acc[im][jn][0], acc[im][jn][1]);
                    *(float2*)&Cs[(row + 8) * 128 + col] = make_float2(acc[im][jn][2], acc[im][jn][3]);
                }
        }
        __syncthreads();
        if (wn >= 2) {
            __half* gih = (__half*)g_i_h4;
            const int cbase = (wn - 2) * 64;
#pragma unroll
            for (int im = 0; im < 4; im++) {
#pragma unroll
                for (int half = 0; half < 2; half++) {
                    int row = wm * 64 + im * 16 + (lane >> 2) + half * 8;
                    if (m0 + row < cnt) {
                        int grow = ofs + m0 + row;
#pragma unroll
                        for (int jn = 0; jn < 8; jn++) {
                            int col = cbase + jn * 8 + (lane & 3) * 2;
                            float g0 = Cs[row * 128 + col];
                            float g1 = Cs[row * 128 + col + 1];
                            float u0 = acc[im][jn][half * 2];
                            float u1 = acc[im][jn][half * 2 + 1];
                            float v0 = (g0 / (1.f + __expf(-g0))) * u0;
                            float v1 = (g1 / (1.f + __expf(-g1))) * u1;
                            __half2 hh = __floats2half2_rn(v0, v1);
                            size_t gi = (size_t)grow * I_DIM + nb * 128 + col;
                            *(uint32_t*)(gih + gi) = *reinterpret_cast<uint32_t*>(&hh);
                        }
                    }
                }
            }
        }
    } else {
        __half* gyh = (__half*)g_y_h4;
#pragma unroll
        for (int im = 0; im < 4; im++) {
#pragma unroll
            for (int half = 0; half < 2; half++) {
                int r = m0 + wm * 64 + im * 16 + (lane >> 2) + half * 8;
                if (r < cnt) {
                    int gr = ofs + r;
                    float wgt = g_rows_w[gr];
                    int t = g_rows_tok[gr], sl = g_rows_slot[gr];
                    size_t base = ((size_t)t * KSEL + sl) * H_DIM + nb * 256 + wn * 64;
#pragma unroll
                    for (int jn = 0; jn < 8; jn++) {
                        int col = jn * 8 + (lane & 3) * 2;
                        __half2 hv = __floats2half2_rn(acc[im][jn][half * 2] * wgt,
                                                       acc[im][jn][half * 2 + 1] * wgt);
                        *(uint32_t*)(gyh + base + col) = *reinterpret_cast<uint32_t*>(&hv);
                    }
                }
            }
        }
    }
}

// ---------------- combine (fp16 y slots -> fp32 out) ------------------------
__global__ void combine_kernel(float* __restrict__ out) {
    int i = blockIdx.x * blockDim.x + threadIdx.x;   // over T*H/4
    if (i >= T_TOK * H_DIM / 4) return;
    const int nv = H_DIM / 4;
    int t = i / nv, n = i - t * nv;
    const uint2* yh = (const uint2*)g_y_h4;          // 4 fp16 per uint2
    uint2 a = yh[((size_t)t * KSEL + 0) * nv + n];
    uint2 b = yh[((size_t)t * KSEL + 1) * nv + n];
    __half2 a0 = *reinterpret_cast<__half2*>(&a.x);
    __half2 a1 = *reinterpret_cast<__half2*>(&a.y);
    __half2 b0 = *reinterpret_cast<__half2*>(&b.x);
    __half2 b1 = *reinterpret_cast<__half2*>(&b.y);
    float2 fa0 = __half22float2(a0), fa1 = __half22float2(a1);
    float2 fb0 = __half22float2(b0), fb1 = __half22float2(b1);
    float4 o;
    o.x = fa0.x + fb0.x; o.y = fa0.y + fb0.y;
    o.z = fa1.x + fb1.x; o.w = fa1.y + fb1.y;
    ((float4*)out)[i] = o;
}

__global__ void aux_kernel(float* __restrict__ aux_out) {
    if (threadIdx.x == 0) {
        float aux = 0.f;
        float invT = 1.f / (float)T_TOK;
        for (int e = 0; e < E_NUM; e++)
            aux += (g_prob_sum[e] * invT) * ((float)g_counts[e] * invT);
        aux_out[0] = aux * (float)E_NUM * AUX_COEF;
    }
}

// ---------------- launch ----------------
extern "C" void kernel_launch(void* const* d_in, const int* in_sizes, int n_in,
                              void* d_out, int out_size) {
    const float* x   = (const float*)d_in[0];
    const float* gw  = (const float*)d_in[1];
    const float* gup = (const float*)d_in[2];
    const float* dwn = (const float*)d_in[3];
    float* out = (float*)d_out;

    const long long need_logits = (long long)T_TOK * H_DIM + (long long)T_TOK * E_NUM;
    float* logits = ((long long)out_size >= need_logits) ? out + (size_t)T_TOK * H_DIM : nullptr;
    float* auxp   = ((long long)out_size >= need_logits + 1) ? logits + (size_t)T_TOK * E_NUM : nullptr;

    cudaFuncSetAttribute(moe_gemm_mma<H_DIM, 1>, cudaFuncAttributeMaxDynamicSharedMemorySize, SMEM_TOT);
    cudaFuncSetAttribute(moe_gemm_mma<I_DIM, 2>, cudaFuncAttributeMaxDynamicSharedMemorySize, SMEM_TOT);

    // 1: fused fp32->fp16 convert (also zeroes router accumulators)
    {
        long long tot = (long long)N4_X + N4_W1 + N4_W2;
        split_all_kernel<<<(unsigned)((tot + 255) / 256), 256>>>(
            (const float4*)x, (const float4*)gup, (const float4*)dwn);
    }
    // 2: router
    router_kernel<<<T_TOK, 256>>>(x, gw, logits);
    // 3: offsets + scatter (single block)
    offsets_scatter_kernel<<<1, 1024>>>();
    // 4: GEMM1 (gathered x) @ gate_up^T, fused silu -> g_i (fp16)
    moe_gemm_mma<H_DIM, 1><<<dim3(32, I_DIM / 128, E_NUM), 256, SMEM_TOT>>>();
    // 5: GEMM2 inter @ down^T, scaled, scattered -> g_y (fp16)
    moe_gemm_mma<I_DIM, 2><<<dim3(32, H_DIM / 256, E_NUM), 256, SMEM_TOT>>>();
    // 6: combine
    combine_kernel<<<(T_TOK * H_DIM / 4 + 255) / 256, 256>>>(out);
    // 7: aux
    if (auxp) aux_kernel<<<1, 32>>>(auxp);
}

// round 17
// speedup vs baseline: 1.1181x; 1.1181x over previous
#include <cuda_runtime.h>
#include <cuda_fp16.h>
#include <math.h>
#include <stdint.h>

#define T_TOK 4096
#define H_DIM 2048
#define E_NUM 8
#define I_DIM 768
#define KSEL  2
#define N1    (2*I_DIM)
#define ROWS_TOTAL (T_TOK*KSEL)
#define AUX_COEF 0.001f

__device__ uint4 g_x_h4[(size_t)T_TOK * H_DIM / 8];
__device__ uint4 g_w1_h4[(size_t)E_NUM * N1 * H_DIM / 8];
__device__ uint4 g_w2_h4[(size_t)E_NUM * H_DIM * I_DIM / 8];
__device__ uint4 g_i_h4[(size_t)ROWS_TOTAL * I_DIM / 8];
__device__ uint4 g_y_h4[(size_t)ROWS_TOTAL * H_DIM / 8];
__device__ int   g_sel[ROWS_TOTAL];
__device__ float g_wt[ROWS_TOTAL];
__device__ int   g_counts[E_NUM];
__device__ int   g_ofs[E_NUM];
__device__ int   g_cursor[E_NUM];
__device__ int   g_rows_tok[ROWS_TOTAL];
__device__ int   g_rows_slot[ROWS_TOTAL];
__device__ float g_rows_w[ROWS_TOTAL];
__device__ float g_prob_sum[E_NUM];

__device__ __forceinline__ uint32_t smem_u32(const void* p) {
    uint32_t a;
    asm("{ .reg .u64 t; cvta.to.shared.u64 t, %1; cvt.u32.u64 %0, t; }" : "=r"(a) : "l"(p));
    return a;
}
__device__ __forceinline__ void ldsm_x4(uint32_t* r, uint32_t addr) {
    asm volatile("ldmatrix.sync.aligned.m8n8.x4.shared.b16 {%0,%1,%2,%3}, [%4];"
        : "=r"(r[0]), "=r"(r[1]), "=r"(r[2]), "=r"(r[3]) : "r"(addr));
}
__device__ __forceinline__ void mma16816(float* c, const uint32_t* a, const uint32_t* b) {
    asm volatile("mma.sync.aligned.m16n8k16.row.col.f32.f16.f16.f32 "
        "{%0,%1,%2,%3}, {%4,%5,%6,%7}, {%8,%9}, {%0,%1,%2,%3};"
        : "+f"(c[0]), "+f"(c[1]), "+f"(c[2]), "+f"(c[3])
        : "r"(a[0]), "r"(a[1]), "r"(a[2]), "r"(a[3]), "r"(b[0]), "r"(b[1]));
}
__device__ __forceinline__ void cpa16(uint32_t dst, const void* src) {
    asm volatile("cp.async.cg.shared.global [%0], [%1], 16;" :: "r"(dst), "l"(src) : "memory");
}
#define CP_COMMIT() asm volatile("cp.async.commit_group;" ::: "memory")
#define CP_WAIT1()  asm volatile("cp.async.wait_group 1;" ::: "memory")

#define N4_X  (T_TOK * H_DIM / 4)
#define N4_W1 (E_NUM * N1 * H_DIM / 4)
#define N4_W2 (E_NUM * H_DIM * I_DIM / 4)

__global__ void init_counters_kernel() {
    if (threadIdx.x < E_NUM) { g_counts[threadIdx.x] = 0; g_prob_sum[threadIdx.x] = 0.f; }
}

__global__ void split_xw1_kernel(const float4* __restrict__ x,
                                 const float4* __restrict__ w1) {
    long long i = (long long)blockIdx.x * blockDim.x + threadIdx.x;
    const float4* src; uint2* hi; long long idx;
    if (i < N4_X)                         { src = x;  hi = (uint2*)g_x_h4;  idx = i; }
    else if (i < (long long)N4_X + N4_W1) { src = w1; hi = (uint2*)g_w1_h4; idx = i - N4_X; }
    else return;
    float4 v = src[idx];
    __half2 hxy = __floats2half2_rn(v.x, v.y);
    __half2 hzw = __floats2half2_rn(v.z, v.w);
    uint2 h;
    h.x = *reinterpret_cast<uint32_t*>(&hxy); h.y = *reinterpret_cast<uint32_t*>(&hzw);
    hi[idx] = h;
}
__global__ void split_w2_kernel(const float4* __restrict__ w2) {
    long long i = (long long)blockIdx.x * blockDim.x + threadIdx.x;
    if (i >= N4_W2) return;
    float4 v = w2[i];
    __half2 hxy = __floats2half2_rn(v.x, v.y);
    __half2 hzw = __floats2half2_rn(v.z, v.w);
    uint2 h;
    h.x = *reinterpret_cast<uint32_t*>(&hxy); h.y = *reinterpret_cast<uint32_t*>(&hzw);
    ((uint2*)g_w2_h4)[i] = h;
}

__global__ void router_kernel(const float* __restrict__ x,
                              const float* __restrict__ gw,
                              float* __restrict__ logits_out) {
    const int t = blockIdx.x;
    const float* xr = x + (size_t)t * H_DIM;
    float acc[E_NUM];
#pragma unroll
    for (int e = 0; e < E_NUM; e++) acc[e] = 0.f;
    for (int h = threadIdx.x; h < H_DIM; h += blockDim.x) {
        float xv = xr[h];
        const float4 g0 = *(const float4*)(gw + (size_t)h * E_NUM);
        const float4 g1 = *(const float4*)(gw + (size_t)h * E_NUM + 4);
        acc[0] += xv * g0.x; acc[1] += xv * g0.y; acc[2] += xv * g0.z; acc[3] += xv * g0.w;
        acc[4] += xv * g1.x; acc[5] += xv * g1.y; acc[6] += xv * g1.z; acc[7] += xv * g1.w;
    }
#pragma unroll
    for (int e = 0; e < E_NUM; e++)
#pragma unroll
        for (int o = 16; o; o >>= 1) acc[e] += __shfl_xor_sync(0xffffffffu, acc[e], o);
    __shared__ float red[E_NUM][8];
    int warp = threadIdx.x >> 5, lane = threadIdx.x & 31;
    if (lane == 0)
#pragma unroll
        for (int e = 0; e < E_NUM; e++) red[e][warp] = acc[e];
    __syncthreads();
    if (threadIdx.x == 0) {
        float lg[E_NUM];
#pragma unroll
        for (int e = 0; e < E_NUM; e++) {
            float s = 0.f;
#pragma unroll
            for (int w = 0; w < 8; w++) s += red[e][w];
            lg[e] = s;
        }
        if (logits_out)
#pragma unroll
            for (int e = 0; e < E_NUM; e++) logits_out[(size_t)t * E_NUM + e] = lg[e];
        float mx = lg[0];
#pragma unroll
        for (int e = 1; e < E_NUM; e++) mx = fmaxf(mx, lg[e]);
        float p[E_NUM], s = 0.f;
#pragma unroll
        for (int e = 0; e < E_NUM; e++) { p[e] = expf(lg[e] - mx); s += p[e]; }
        float inv = 1.f / s;
#pragma unroll
        for (int e = 0; e < E_NUM; e++) { p[e] *= inv; atomicAdd(&g_prob_sum[e], p[e]); }
        bool used[E_NUM];
#pragma unroll
        for (int e = 0; e < E_NUM; e++) used[e] = false;
        int si[KSEL]; float sp[KSEL]; float wsum = 0.f;
#pragma unroll
        for (int k = 0; k < KSEL; k++) {
            int bi = -1; float bv = -1.f;
#pragma unroll
            for (int e = 0; e < E_NUM; e++)
                if (!used[e] && p[e] > bv) { bv = p[e]; bi = e; }
            used[bi] = true; si[k] = bi; sp[k] = bv; wsum += bv;
        }
        float winv = 1.f / wsum;
#pragma unroll
        for (int k = 0; k < KSEL; k++) {
            g_sel[t * KSEL + k] = si[k];
            g_wt[t * KSEL + k]  = sp[k] * winv;
            atomicAdd(&g_counts[si[k]], 1);
        }
    }
}

__global__ void offsets_scatter_kernel() {
    if (threadIdx.x == 0) {
        int run = 0;
        for (int e = 0; e < E_NUM; e++) { g_ofs[e] = run; g_cursor[e] = run; run += g_counts[e]; }
    }
    __syncthreads();
    for (int i = threadIdx.x; i < ROWS_TOTAL; i += blockDim.x) {
        int e = g_sel[i];
        int p = atomicAdd(&g_cursor[e], 1);
        g_rows_tok[p]  = i / KSEL;
        g_rows_slot[p] = i % KSEL;
        g_rows_w[p]    = g_wt[i];
    }
}

#define SROW 72
#define A_ARR (128 * 144)
#define B_ARR (128 * 144)
#define OFF_A  0
#define OFF_B  A_ARR
#define STG_BYTES (A_ARR + B_ARR)
#define SMEM_TOT (2 * STG_BYTES)

template<int KDIM, int MODE>
__global__ void __launch_bounds__(256, 2)
moe_gemm_mma() {
    constexpr int NCH  = KDIM / 64;
    constexpr int NDIM = (MODE == 1) ? N1 : H_DIM;
    const __half* a_h = (MODE == 1) ? (const __half*)g_x_h4 : (const __half*)g_i_h4;
    const __half* b_h = (MODE == 1) ? (const __half*)g_w1_h4 : (const __half*)g_w2_h4;

    const int e   = blockIdx.z;
    const int cnt = g_counts[e];
    const int m0  = blockIdx.x * 128;
    if (m0 >= cnt) return;
    const int nb  = blockIdx.y;
    const int ofs = g_ofs[e];

    extern __shared__ char smem[];
    const uint32_t sb = smem_u32(smem);

    const int tid  = threadIdx.x;
    const int wid  = tid >> 5;
    const int lane = tid & 31;
    const int wm   = wid & 1;
    const int wn   = wid >> 1;

    const int q16 = tid & 7;
    const int r0  = tid >> 3;
    const uint32_t soff0 = (uint32_t)(r0 * 144 + q16 * 16);
    uint32_t arow[4], brow[4];
#pragma unroll
    for (int i = 0; i < 4; i++) {
        int r = i * 32 + r0;
        int lm = m0 + r; if (lm > cnt - 1) lm = cnt - 1;
        if (MODE == 1) arow[i] = (uint32_t)__ldg(&g_rows_tok[ofs + lm]) * H_DIM + q16 * 8;
        else           arow[i] = (uint32_t)(ofs + lm) * I_DIM + q16 * 8;
        int gn;
        if (MODE == 1) gn = (r < 64) ? (nb * 64 + r) : (I_DIM + nb * 64 + (r - 64));
        else           gn = nb * 128 + r;
        brow[i] = (uint32_t)((e * NDIM + gn) * KDIM) + q16 * 8;
    }

    auto issue_stage = [&](int c) {
        if (c < NCH) {
            const int kt = c * 64;
            const uint32_t st = sb + (uint32_t)(c & 1) * STG_BYTES;
#pragma unroll
            for (int i = 0; i < 4; i++) {
                cpa16(st + OFF_A + soff0 + i * (32 * 144), a_h + arow[i] + kt);
                cpa16(st + OFF_B + soff0 + i * (32 * 144), b_h + brow[i] + kt);
            }
        }
        CP_COMMIT();
    };

    const uint32_t a_base = ((wm * 64 + (lane & 15)) * SROW + (lane >> 4) * 8) * 2;
    const uint32_t b_base = ((wn * 32 + ((lane >> 4) << 3) + (lane & 7)) * SROW + ((lane >> 3) & 1) * 8) * 2;

    float acc[4][4][4];
#pragma unroll
    for (int i = 0; i < 4; i++)
#pragma unroll
        for (int j = 0; j < 4; j++)
#pragma unroll
            for (int k = 0; k < 4; k++) acc[i][j][k] = 0.f;

    issue_stage(0); issue_stage(1);

    for (int c = 0; c < NCH; c++) {
        CP_WAIT1();
        __syncthreads();

        const uint32_t stg = sb + (uint32_t)(c & 1) * STG_BYTES;
#pragma unroll
        for (int kk = 0; kk < 4; kk++) {
            const uint32_t koff = kk * 32;
            uint32_t af[4][4], bf[2][4];
#pragma unroll
            for (int im = 0; im < 4; im++)
                ldsm_x4(af[im], stg + OFF_A + a_base + im * (16 * SROW * 2) + koff);
#pragma unroll
            for (int g = 0; g < 2; g++)
                ldsm_x4(bf[g], stg + OFF_B + b_base + g * (16 * SROW * 2) + koff);
#pragma unroll
            for (int im = 0; im < 4; im++)
#pragma unroll
                for (int g = 0; g < 2; g++) {
                    mma16816(acc[im][g * 2 + 0], af[im], &bf[g][0]);
                    mma16816(acc[im][g * 2 + 1], af[im], &bf[g][2]);
                }
        }
        __syncthreads();
        issue_stage(c + 2);
    }

    if (MODE == 1) {
        float* Cs = (float*)smem;
        if (wn < 2) {
#pragma unroll
            for (int im = 0; im < 4; im++)
#pragma unroll
                for (int jn = 0; jn < 4; jn++) {
                    int row = wm * 64 + im * 16 + (lane >> 2);
                    int col = wn * 32 + jn * 8 + (lane & 3) * 2;
                    *(float2*)&Cs[row * 64 + col]       = make_float2(acc[im][jn][0], acc[im][jn][1]);
                    *(float2*)&Cs[(row + 8) * 64 + col] = make_float2(acc[im][jn][2], acc[im][jn][3]);
                }
        }
        __syncthreads();
        if (wn >= 2) {
            __half* gih = (__half*)g_i_h4;
            const int cbase = (wn - 2) * 32;
#pragma unroll
            for (int im = 0; im < 4; im++) {
#pragma unroll
                for (int half = 0; half < 2; half++) {
                    int row = wm * 64 + im * 16 + (lane >> 2) + half * 8;
                    if (m0 + row < cnt) {
                        int grow = ofs + m0 + row;
#pragma unroll
                        for (int jn = 0; jn < 4; jn++) {
                            int col = cbase + jn * 8 + (lane & 3) * 2;
                            float g0 = Cs[row * 64 + col];
                            float g1 = Cs[row * 64 + col + 1];
                            float u0 = acc[im][jn][half * 2];
                            float u1 = acc[im][jn][half * 2 + 1];
                            float v0 = (g0 / (1.f + __expf(-g0))) * u0;
                            float v1 = (g1 / (1.f + __expf(-g1))) * u1;
                            __half2 hh = __floats2half2_rn(v0, v1);
                            size_t gi = (size_t)grow * I_DIM + nb * 64 + col;
                            *(uint32_t*)(gih + gi) = *reinterpret_cast<uint32_t*>(&hh);
                        }
                    }
                }
            }
        }
    } else {
        __half* gyh = (__half*)g_y_h4;
#pragma unroll
        for (int im = 0; im < 4; im++) {
#pragma unroll
            for (int half = 0; half < 2; half++) {
                int r = m0 + wm * 64 + im * 16 + (lane >> 2) + half * 8;
                if (r < cnt) {
                    int gr = ofs + r;
                    float wgt = g_rows_w[gr];
                    int t = g_rows_tok[gr], sl = g_rows_slot[gr];
                    size_t base = ((size_t)t * KSEL + sl) * H_DIM + nb * 128 + wn * 32;
#pragma unroll
                    for (int jn = 0; jn < 4; jn++) {
                        int col = jn * 8 + (lane & 3) * 2;
                        __half2 hv = __floats2half2_rn(acc[im][jn][half * 2] * wgt,
                                                       acc[im][jn][half * 2 + 1] * wgt);
                        *(uint32_t*)(gyh + base + col) = *reinterpret_cast<uint32_t*>(&hv);
                    }
                }
            }
        }
    }
}

__global__ void combine_kernel(float* __restrict__ out) {
    int i = blockIdx.x * blockDim.x + threadIdx.x;
    if (i >= T_TOK * H_DIM / 4) return;
    const int nv = H_DIM / 4;
    int t = i / nv, n = i - t * nv;
    const uint2* yh = (const uint2*)g_y_h4;
    uint2 a = yh[((size_t)t * KSEL + 0) * nv + n];
    uint2 b = yh[((size_t)t * KSEL + 1) * nv + n];
    __half2 a0 = *reinterpret_cast<__half2*>(&a.x);
    __half2 a1 = *reinterpret_cast<__half2*>(&a.y);
    __half2 b0 = *reinterpret_cast<__half2*>(&b.x);
    __half2 b1 = *reinterpret_cast<__half2*>(&b.y);
    float2 fa0 = __half22float2(a0), fa1 = __half22float2(a1);
    float2 fb0 = __half22float2(b0), fb1 = __half22float2(b1);
    float4 o;
    o.x = fa0.x + fb0.x; o.y = fa0.y + fb0.y;
    o.z = fa1.x + fb1.x; o.w = fa1.y + fb1.y;
    ((float4*)out)[i] = o;
}

__global__ void aux_kernel(float* __restrict__ aux_out) {
    if (threadIdx.x == 0) {
        float aux = 0.f;
        float invT = 1.f / (float)T_TOK;
        for (int e = 0; e < E_NUM; e++)
            aux += (g_prob_sum[e] * invT) * ((float)g_counts[e] * invT);
        aux_out[0] = aux * (float)E_NUM * AUX_COEF;
    }
}

extern "C" void kernel_launch(void* const* d_in, const int* in_sizes, int n_in,
                              void* d_out, int out_size) {
    const float* x   = (const float*)d_in[0];
    const float* gw  = (const float*)d_in[1];
    const float* gup = (const float*)d_in[2];
    const float* dwn = (const float*)d_in[3];
    float* out = (float*)d_out;

    const long long need_logits = (long long)T_TOK * H_DIM + (long long)T_TOK * E_NUM;
    float* logits = ((long long)out_size >= need_logits) ? out + (size_t)T_TOK * H_DIM : nullptr;
    float* auxp   = ((long long)out_size >= need_logits + 1) ? logits + (size_t)T_TOK * E_NUM : nullptr;

    // One-time host-side resources (streams/events only; no device memory).
    static cudaStream_t s2 = nullptr;
    static cudaEvent_t evFork = nullptr, evXW1 = nullptr, evW2 = nullptr;
    if (s2 == nullptr) {
        cudaStreamCreateWithFlags(&s2, cudaStreamNonBlocking);
        cudaEventCreateWithFlags(&evFork, cudaEventDisableTiming);
        cudaEventCreateWithFlags(&evXW1, cudaEventDisableTiming);
        cudaEventCreateWithFlags(&evW2, cudaEventDisableTiming);
        cudaFuncSetAttribute(moe_gemm_mma<H_DIM, 1>, cudaFuncAttributeMaxDynamicSharedMemorySize, SMEM_TOT);
        cudaFuncSetAttribute(moe_gemm_mma<I_DIM, 2>, cudaFuncAttributeMaxDynamicSharedMemorySize, SMEM_TOT);
    }

    // counters zeroed on the main stream BEFORE the fork (router needs them)
    init_counters_kernel<<<1, 32>>>();

    // fork s2
    cudaEventRecord(evFork, 0);
    cudaStreamWaitEvent(s2, evFork, 0);

    // s2: conversions
    {
        long long n1 = (long long)N4_X + N4_W1;
        split_xw1_kernel<<<(unsigned)((n1 + 255) / 256), 256, 0, s2>>>(
            (const float4*)x, (const float4*)gup);
        cudaEventRecord(evXW1, s2);
        split_w2_kernel<<<(unsigned)(((long long)N4_W2 + 255) / 256), 256, 0, s2>>>(
            (const float4*)dwn);
        cudaEventRecord(evW2, s2);
    }

    // main: router -> scatter (overlaps s2 conversions)
    router_kernel<<<T_TOK, 256>>>(x, gw, logits);
    offsets_scatter_kernel<<<1, 1024>>>();

    cudaStreamWaitEvent(0, evXW1, 0);   // x_h + w1_h ready
    moe_gemm_mma<H_DIM, 1><<<dim3(32, I_DIM / 64, E_NUM), 256, SMEM_TOT>>>();

    cudaStreamWaitEvent(0, evW2, 0);    // w2_h ready (converted under GEMM1)
    moe_gemm_mma<I_DIM, 2><<<dim3(32, H_DIM / 128, E_NUM), 256, SMEM_TOT>>>();

    combine_kernel<<<(T_TOK * H_DIM / 4 + 255) / 256, 256>>>(out);
    if (auxp) aux_kernel<<<1, 32>>>(auxp);
}